// round 15
// baseline (speedup 1.0000x reference)
#include <cuda_runtime.h>
#include <cuda_bf16.h>
#include <math.h>
#include <cstdint>

// Problem constants
#define BB      2
#define SS      2048
#define DMODEL  1024
#define NH      16
#define DHEAD   64
#define MROWS   (BB*SS)        // 4096

// ---------------------------------------------------------------------------
// Scratch (device globals; no runtime allocation allowed)
// ---------------------------------------------------------------------------
__device__ float g_cos[SS*(DHEAD/2)];
__device__ float g_sin[SS*(DHEAD/2)];

__device__ __nv_bfloat16 g_xhi [MROWS*DMODEL];
__device__ __nv_bfloat16 g_xlo [MROWS*DMODEL];
__device__ __nv_bfloat16 g_whi[4][DMODEL*DMODEL];
__device__ __nv_bfloat16 g_wlo[4][DMODEL*DMODEL];

__device__ __nv_bfloat16 g_qhi[MROWS*DMODEL];
__device__ __nv_bfloat16 g_qlo[MROWS*DMODEL];
__device__ __nv_bfloat16 g_khi[MROWS*DMODEL];
__device__ __nv_bfloat16 g_klo[MROWS*DMODEL];
__device__ __nv_bfloat16 g_vhi[MROWS*DMODEL];
__device__ __nv_bfloat16 g_vlo[MROWS*DMODEL];
__device__ __nv_bfloat16 g_aohi[MROWS*DMODEL];
__device__ __nv_bfloat16 g_aolo[MROWS*DMODEL];

// ---------------------------------------------------------------------------
// PTX helpers (sm_80-era only; ptxas target rejects tcgen05)
// ---------------------------------------------------------------------------
__device__ __forceinline__ uint32_t smem_to_u32(const void* smem_ptr) {
    uint32_t addr;
    asm("{ .reg .u64 tmp; cvta.to.shared.u64 tmp, %1; cvt.u32.u64 %0, tmp; }"
        : "=r"(addr) : "l"(smem_ptr));
    return addr;
}

__device__ __forceinline__ void cp16(uint32_t dst, const void* src) {
    asm volatile("cp.async.cg.shared.global [%0], [%1], 16;" :: "r"(dst), "l"(src));
}
#define CP_COMMIT() asm volatile("cp.async.commit_group;" ::: "memory")
#define CP_WAIT1()  asm volatile("cp.async.wait_group 1;" ::: "memory")

__device__ __forceinline__ void ldsm_x4(uint32_t a[4], uint32_t addr) {
    asm volatile("ldmatrix.sync.aligned.m8n8.x4.shared.b16 {%0,%1,%2,%3}, [%4];"
        : "=r"(a[0]), "=r"(a[1]), "=r"(a[2]), "=r"(a[3]) : "r"(addr));
}
__device__ __forceinline__ void ldsm_x4_t(uint32_t a[4], uint32_t addr) {
    asm volatile("ldmatrix.sync.aligned.m8n8.x4.trans.shared.b16 {%0,%1,%2,%3}, [%4];"
        : "=r"(a[0]), "=r"(a[1]), "=r"(a[2]), "=r"(a[3]) : "r"(addr));
}

__device__ __forceinline__ void mma16816(float c[4], const uint32_t a[4],
                                         uint32_t b0, uint32_t b1) {
    asm volatile("mma.sync.aligned.m16n8k16.row.col.f32.bf16.bf16.f32 "
        "{%0,%1,%2,%3}, {%4,%5,%6,%7}, {%8,%9}, {%0,%1,%2,%3};"
        : "+f"(c[0]), "+f"(c[1]), "+f"(c[2]), "+f"(c[3])
        : "r"(a[0]), "r"(a[1]), "r"(a[2]), "r"(a[3]), "r"(b0), "r"(b1));
}

// split fp32 pair into bf16 hi/lo packed words
__device__ __forceinline__ void packhl(float x, float y, uint32_t& hi, uint32_t& lo) {
    __nv_bfloat16 hx = __float2bfloat16(x), hy = __float2bfloat16(y);
    __nv_bfloat16 lx = __float2bfloat16(x - __bfloat162float(hx));
    __nv_bfloat16 ly = __float2bfloat16(y - __bfloat162float(hy));
    __nv_bfloat162 H = __halves2bfloat162(hx, hy);
    __nv_bfloat162 L = __halves2bfloat162(lx, ly);
    hi = *(uint32_t*)&H; lo = *(uint32_t*)&L;
}

// ---------------------------------------------------------------------------
// RoPE table
// ---------------------------------------------------------------------------
__global__ void rope_table_kernel(const int* __restrict__ pos)
{
    int idx = blockIdx.x * 256 + threadIdx.x;
    if (idx >= SS * (DHEAD/2)) return;
    int s  = idx >> 5;
    int pr = idx & 31;
    float p   = (float)pos[s];
    float ex  = (float)(2 * pr) * (1.0f / 64.0f);
    float inv = powf(10000.0f, -ex);
    float ang = p * inv;
    float sn, cs;
    sincosf(ang, &sn, &cs);
    g_cos[idx] = cs;
    g_sin[idx] = sn;
}

// ---------------------------------------------------------------------------
// fp32 -> bf16 hi/lo split kernels (inputs only)
// ---------------------------------------------------------------------------
__device__ __forceinline__ void split4(const float4 v, __nv_bfloat16* hi,
                                       __nv_bfloat16* lo, size_t i4)
{
    float f[4] = {v.x, v.y, v.z, v.w};
    __nv_bfloat16 h[4], l[4];
#pragma unroll
    for (int j = 0; j < 4; ++j) {
        h[j] = __float2bfloat16(f[j]);
        l[j] = __float2bfloat16(f[j] - __bfloat162float(h[j]));
    }
    ((__nv_bfloat162*)hi)[2*i4]   = __halves2bfloat162(h[0], h[1]);
    ((__nv_bfloat162*)hi)[2*i4+1] = __halves2bfloat162(h[2], h[3]);
    ((__nv_bfloat162*)lo)[2*i4]   = __halves2bfloat162(l[0], l[1]);
    ((__nv_bfloat162*)lo)[2*i4+1] = __halves2bfloat162(l[2], l[3]);
}

__global__ __launch_bounds__(256) void split_x_kernel(const float* __restrict__ x)
{
    size_t i = (size_t)blockIdx.x * 256 + threadIdx.x;
    split4(((const float4*)x)[i], g_xhi, g_xlo, i);
}

__global__ __launch_bounds__(256) void split_w_kernel(
    const float* __restrict__ Qw, const float* __restrict__ Kw,
    const float* __restrict__ Vw, const float* __restrict__ Ow)
{
    const int w = blockIdx.y;
    const float* src = (w == 0) ? Qw : (w == 1) ? Kw : (w == 2) ? Vw : Ow;
    size_t i = (size_t)blockIdx.x * 256 + threadIdx.x;
    split4(((const float4*)src)[i], g_whi[w], g_wlo[w], i);
}

// ---------------------------------------------------------------------------
// HMMA bf16x3 GEMM (measured-stable configuration, unchanged).
// CTA 128x256, BK=32, 3-stage cp.async pipeline, 256 threads, 8 warps 64x64.
// ---------------------------------------------------------------------------
#define BM 128
#define BN 256
#define BKG 32
#define NKIT (DMODEL/BKG)      // 32
#define ROWB 80
#define OFFA_HI 0
#define OFFA_LO (128*ROWB)             // 10240
#define OFFB_HI (2*128*ROWB)           // 20480
#define OFFB_LO (OFFB_HI + 256*ROWB)   // 40960
#define STAGEB  (OFFB_LO + 256*ROWB)   // 61440
#define NSTG 3
#define GEMM_SMEM_BYTES (NSTG*STAGEB)  // 184320

__device__ __forceinline__ void issue_stage(uint32_t sbase,
    const __nv_bfloat16* __restrict__ Ahi, const __nv_bfloat16* __restrict__ Alo,
    const __nv_bfloat16* __restrict__ Bhi, const __nv_bfloat16* __restrict__ Blo,
    int m0, int n0, int k0, int tid)
{
#pragma unroll
    for (int i2 = 0; i2 < 2; ++i2) {
        const int i = tid + i2 * 256;
        const int r = i >> 2, c = i & 3;
        const uint32_t so = (uint32_t)(r * ROWB + c * 16);
        const size_t go = (size_t)(m0 + r) * DMODEL + k0 + c * 8;
        cp16(sbase + OFFA_HI + so, Ahi + go);
        cp16(sbase + OFFA_LO + so, Alo + go);
    }
#pragma unroll
    for (int i2 = 0; i2 < 4; ++i2) {
        const int i = tid + i2 * 256;
        const int r = i >> 2, c = i & 3;
        const uint32_t so = (uint32_t)(r * ROWB + c * 16);
        const size_t go = (size_t)(n0 + r) * DMODEL + k0 + c * 8;
        cp16(sbase + OFFB_HI + so, Bhi + go);
        cp16(sbase + OFFB_LO + so, Blo + go);
    }
}

__device__ __forceinline__ void tc_gemm(
    const __nv_bfloat16* __restrict__ Ahi, const __nv_bfloat16* __restrict__ Alo,
    const __nv_bfloat16* __restrict__ Bhi, const __nv_bfloat16* __restrict__ Blo,
    float* __restrict__ Cf, __nv_bfloat16* __restrict__ Chi,
    __nv_bfloat16* __restrict__ Clo, const bool do_rope)
{
    extern __shared__ char gsm[];
    const uint32_t sb = smem_to_u32(gsm);

    const int tid = threadIdx.x;
    const int wid = tid >> 5;
    const int lid = tid & 31;
    const int wm  = wid & 1;
    const int wn  = wid >> 1;
    const int m0  = blockIdx.y * BM;
    const int n0  = blockIdx.x * BN;

    float acc[4][8][4];
#pragma unroll
    for (int mt = 0; mt < 4; ++mt)
#pragma unroll
        for (int nb = 0; nb < 8; ++nb)
#pragma unroll
            for (int j = 0; j < 4; ++j) acc[mt][nb][j] = 0.0f;

    const uint32_t a_lane = (uint32_t)((lid & 15) * ROWB + (lid >> 4) * 16);
    const uint32_t b_lane = (uint32_t)(((lid & 7) + ((lid >> 4) << 3)) * ROWB
                                       + ((lid >> 3) & 1) * 16);

    issue_stage(sb,          Ahi, Alo, Bhi, Blo, m0, n0, 0,   tid); CP_COMMIT();
    issue_stage(sb + STAGEB, Ahi, Alo, Bhi, Blo, m0, n0, BKG, tid); CP_COMMIT();

    int stg = 0;
#pragma unroll 1
    for (int it = 0; it < NKIT; ++it) {
        CP_WAIT1();
        __syncthreads();

        const uint32_t st = sb + (uint32_t)stg * STAGEB;
#pragma unroll
        for (int ks = 0; ks < 2; ++ks) {
            const uint32_t kso = (uint32_t)(ks * 32);
            uint32_t ah[4][4], al[4][4], bh[4][4], bl[4][4];
#pragma unroll
            for (int mt = 0; mt < 4; ++mt) {
                const uint32_t abase = st + (uint32_t)((wm*64 + mt*16) * ROWB) + kso + a_lane;
                ldsm_x4(ah[mt], abase + OFFA_HI);
                ldsm_x4(al[mt], abase + OFFA_LO);
            }
#pragma unroll
            for (int p = 0; p < 4; ++p) {
                const uint32_t bbase = st + (uint32_t)((wn*64 + p*16) * ROWB) + kso + b_lane;
                ldsm_x4(bh[p], bbase + OFFB_HI);
                ldsm_x4(bl[p], bbase + OFFB_LO);
            }
#pragma unroll
            for (int mt = 0; mt < 4; ++mt)
#pragma unroll
                for (int nb = 0; nb < 8; ++nb) {
                    const int p = nb >> 1, o = (nb & 1) * 2;
                    mma16816(acc[mt][nb], ah[mt], bh[p][o], bh[p][o+1]);
                }
#pragma unroll
            for (int mt = 0; mt < 4; ++mt)
#pragma unroll
                for (int nb = 0; nb < 8; ++nb) {
                    const int p = nb >> 1, o = (nb & 1) * 2;
                    mma16816(acc[mt][nb], ah[mt], bl[p][o], bl[p][o+1]);
                }
#pragma unroll
            for (int mt = 0; mt < 4; ++mt)
#pragma unroll
                for (int nb = 0; nb < 8; ++nb) {
                    const int p = nb >> 1, o = (nb & 1) * 2;
                    mma16816(acc[mt][nb], al[mt], bh[p][o], bh[p][o+1]);
                }
        }

        if (it + 2 < NKIT) {
            int rstg = stg + 2; if (rstg >= NSTG) rstg -= NSTG;
            issue_stage(sb + (uint32_t)rstg * STAGEB,
                        Ahi, Alo, Bhi, Blo, m0, n0, (it + 2) * BKG, tid);
        }
        CP_COMMIT();
        if (++stg == NSTG) stg = 0;
    }

#pragma unroll
    for (int mt = 0; mt < 4; ++mt) {
        const int row0 = m0 + wm*64 + mt*16 + (lid >> 2);
#pragma unroll
        for (int nb = 0; nb < 8; ++nb) {
            const int col = n0 + wn*64 + nb*8 + 2*(lid & 3);
            float v0 = acc[mt][nb][0], v1 = acc[mt][nb][1];
            float v2 = acc[mt][nb][2], v3 = acc[mt][nb][3];
            if (do_rope) {
                const int pr = (col & 63) >> 1;
                {
                    const int s = row0 & (SS - 1);
                    const float cs = g_cos[s*32 + pr], sn = g_sin[s*32 + pr];
                    const float x0 = v0, x1 = v1;
                    v0 = x0*cs - x1*sn;  v1 = x0*sn + x1*cs;
                }
                {
                    const int s = (row0 + 8) & (SS - 1);
                    const float cs = g_cos[s*32 + pr], sn = g_sin[s*32 + pr];
                    const float x0 = v2, x1 = v3;
                    v2 = x0*cs - x1*sn;  v3 = x0*sn + x1*cs;
                }
            }
            if (Cf) {
                *(float2*)(Cf + (size_t)row0       * DMODEL + col) = make_float2(v0, v1);
                *(float2*)(Cf + (size_t)(row0 + 8) * DMODEL + col) = make_float2(v2, v3);
            } else {
                uint32_t h0, l0, h1, l1;
                packhl(v0, v1, h0, l0);
                packhl(v2, v3, h1, l1);
                *(uint32_t*)(Chi + (size_t)row0       * DMODEL + col) = h0;
                *(uint32_t*)(Clo + (size_t)row0       * DMODEL + col) = l0;
                *(uint32_t*)(Chi + (size_t)(row0 + 8) * DMODEL + col) = h1;
                *(uint32_t*)(Clo + (size_t)(row0 + 8) * DMODEL + col) = l1;
            }
        }
    }
}

__global__ __launch_bounds__(256)
void qkv_gemm_kernel()
{
    const int z = blockIdx.z;
    __nv_bfloat16* Chi = (z == 0) ? g_qhi : (z == 1) ? g_khi : g_vhi;
    __nv_bfloat16* Clo = (z == 0) ? g_qlo : (z == 1) ? g_klo : g_vlo;
    tc_gemm(g_xhi, g_xlo, g_whi[z], g_wlo[z], nullptr, Chi, Clo, z < 2);
}

__global__ __launch_bounds__(256)
void oproj_gemm_kernel(float* __restrict__ out)
{
    tc_gemm(g_aohi, g_aolo, g_whi[3], g_wlo[3], out, nullptr, nullptr, false);
}

// ---------------------------------------------------------------------------
// Flash attention, HMMA bf16x3 — 2 CTAs/SM variant:
//   Q fragments reloaded from smem each tile (frees 32 regs), 2-stage KV
//   ring (108 KB smem/CTA), __launch_bounds__(256,2) -> <=128 regs so two
//   independent CTAs per SM cover each other's softmax/barrier phases.
// CTA: 128 q-rows (8 warps x 16), key tiles of 64.
// ---------------------------------------------------------------------------
#define ATM 128
#define ATN 64
#define AROWB 144
#define AQHI_OFF 0
#define AQLO_OFF (128*AROWB)            // 18432
#define ASTG_OFF (2*128*AROWB)          // 36864
#define SK_HI 0
#define SK_LO (64*AROWB)                // 9216
#define SV_HI (2*64*AROWB)
#define SV_LO (3*64*AROWB)
#define ASTGB (4*64*AROWB)              // 36864
#define ANSTG 2
#define ATTN_SMEM_B (ASTG_OFF + ANSTG*ASTGB)  // 110592

__device__ __forceinline__ void issue_kv(uint32_t st,
    const __nv_bfloat16* __restrict__ kh, const __nv_bfloat16* __restrict__ kl,
    const __nv_bfloat16* __restrict__ vh, const __nv_bfloat16* __restrict__ vl,
    int n0, int tid)
{
#pragma unroll
    for (int i2 = 0; i2 < 2; ++i2) {
        const int i = tid + i2 * 256;
        const int r = i >> 3, c = i & 7;
        const size_t go = (size_t)(n0 + r) * DMODEL + c * 8;
        const uint32_t so = (uint32_t)(r * AROWB + c * 16);
        cp16(st + SK_HI + so, kh + go);
        cp16(st + SK_LO + so, kl + go);
        cp16(st + SV_HI + so, vh + go);
        cp16(st + SV_LO + so, vl + go);
    }
}

__global__ __launch_bounds__(256, 2)
void attn_kernel()
{
    extern __shared__ char smb[];
    const uint32_t sb = smem_to_u32(smb);
    const int tid = threadIdx.x;
    const int wid = tid >> 5;
    const int lid = tid & 31;
    const int bh  = blockIdx.y;
    const int b   = bh >> 4, h = bh & 15;
    const int bx  = (int)gridDim.x - 1 - (int)blockIdx.x;   // long blocks first
    const int q0  = bx * ATM;

    const size_t hb = (size_t)(b*SS)*DMODEL + h*DHEAD;
    const __nv_bfloat16* qh_g = g_qhi + hb + (size_t)q0*DMODEL;
    const __nv_bfloat16* ql_g = g_qlo + hb + (size_t)q0*DMODEL;
    const __nv_bfloat16* kh_g = g_khi + hb;
    const __nv_bfloat16* kl_g = g_klo + hb;
    const __nv_bfloat16* vh_g = g_vhi + hb;
    const __nv_bfloat16* vl_g = g_vlo + hb;

    const int ntiles = 2*bx + 2;

    // Prologue: Q (hi+lo) + KV tile 0 in group 0; KV tile 1 in group 1.
#pragma unroll
    for (int i2 = 0; i2 < 4; ++i2) {
        const int i = tid + i2 * 256;
        const int r = i >> 3, c = i & 7;
        const size_t go = (size_t)r * DMODEL + c * 8;
        const uint32_t so = (uint32_t)(r * AROWB + c * 16);
        cp16(sb + AQHI_OFF + so, qh_g + go);
        cp16(sb + AQLO_OFF + so, ql_g + go);
    }
    issue_kv(sb + ASTG_OFF, kh_g, kl_g, vh_g, vl_g, 0, tid);
    CP_COMMIT();
    issue_kv(sb + ASTG_OFF + ASTGB, kh_g, kl_g, vh_g, vl_g, ATN, tid);
    CP_COMMIT();

    CP_WAIT1();      // group 0 (Q + KV0) retired; KV1 in flight
    __syncthreads();

    const uint32_t a_lane = (uint32_t)((lid & 15)*AROWB + (lid >> 4)*16);
    const uint32_t qbase  = sb + (uint32_t)(wid*16*AROWB) + a_lane;
    const uint32_t b_lane = (uint32_t)(((lid & 7) + ((lid >> 4) << 3))*AROWB + ((lid >> 3) & 1)*16);
    const uint32_t v_lane = (uint32_t)(((lid & 7) + (((lid >> 3) & 1) << 3))*AROWB + (lid >> 4)*16);
    const int rowq = q0 + wid*16 + (lid >> 2);

    float m0v = -1e30f, m1v = -1e30f, l0s = 0.0f, l1s = 0.0f;
    float oacc[8][4];
#pragma unroll
    for (int nb = 0; nb < 8; ++nb)
#pragma unroll
        for (int j = 0; j < 4; ++j) oacc[nb][j] = 0.0f;

#pragma unroll 1
    for (int jt = 0; jt < ntiles; ++jt) {
        const uint32_t st = sb + ASTG_OFF + (uint32_t)(jt & 1) * ASTGB;

        // S = Q @ K^T (bf16x3); Q fragments reloaded from smem per k-step.
        float c[8][4];
#pragma unroll
        for (int nb = 0; nb < 8; ++nb)
#pragma unroll
            for (int j = 0; j < 4; ++j) c[nb][j] = 0.0f;

#pragma unroll
        for (int ks = 0; ks < 4; ++ks) {
            uint32_t qh4[4], ql4[4];
            const uint32_t qa = qbase + (uint32_t)(ks*32);
            ldsm_x4(qh4, qa + AQHI_OFF);
            ldsm_x4(ql4, qa + AQLO_OFF);
#pragma unroll
            for (int g = 0; g < 4; ++g) {
                uint32_t kh4[4], kl4[4];
                const uint32_t kb = st + (uint32_t)(g*16*AROWB + ks*32) + b_lane;
                ldsm_x4(kh4, kb + SK_HI);
                ldsm_x4(kl4, kb + SK_LO);
#pragma unroll
                for (int hf = 0; hf < 2; ++hf) {
                    const int nb = g*2 + hf;
                    mma16816(c[nb], qh4, kh4[hf*2], kh4[hf*2+1]);
                    mma16816(c[nb], qh4, kl4[hf*2], kl4[hf*2+1]);
                    mma16816(c[nb], ql4, kh4[hf*2], kh4[hf*2+1]);
                }
            }
        }

        // online softmax (rows rowq, rowq+8)
        const int n0 = jt * ATN;
        const bool nm = (n0 + ATN > q0 + wid*16);
        float rm0 = -1e30f, rm1 = -1e30f;
#pragma unroll
        for (int nb = 0; nb < 8; ++nb)
#pragma unroll
            for (int j = 0; j < 4; ++j) {
                float sv = c[nb][j] * 0.125f;
                if (nm) {
                    const int col = n0 + nb*8 + 2*(lid & 3) + (j & 1);
                    const int row = rowq + (j >> 1) * 8;
                    if (col > row) sv = -1e30f;
                }
                c[nb][j] = sv;
                if (j < 2) rm0 = fmaxf(rm0, sv); else rm1 = fmaxf(rm1, sv);
            }
        rm0 = fmaxf(rm0, __shfl_xor_sync(0xffffffffu, rm0, 1, 4));
        rm0 = fmaxf(rm0, __shfl_xor_sync(0xffffffffu, rm0, 2, 4));
        rm1 = fmaxf(rm1, __shfl_xor_sync(0xffffffffu, rm1, 1, 4));
        rm1 = fmaxf(rm1, __shfl_xor_sync(0xffffffffu, rm1, 2, 4));
        const float mn0 = fmaxf(m0v, rm0), mn1 = fmaxf(m1v, rm1);
        const float al0 = __expf(m0v - mn0), al1 = __expf(m1v - mn1);
        m0v = mn0; m1v = mn1;
        float rs0 = 0.0f, rs1 = 0.0f;
#pragma unroll
        for (int nb = 0; nb < 8; ++nb) {
            float p0 = __expf(c[nb][0] - mn0);
            float p1 = __expf(c[nb][1] - mn0);
            float p2 = __expf(c[nb][2] - mn1);
            float p3 = __expf(c[nb][3] - mn1);
            c[nb][0] = p0; c[nb][1] = p1; c[nb][2] = p2; c[nb][3] = p3;
            rs0 += p0 + p1; rs1 += p2 + p3;
        }
        rs0 += __shfl_xor_sync(0xffffffffu, rs0, 1, 4);
        rs0 += __shfl_xor_sync(0xffffffffu, rs0, 2, 4);
        rs1 += __shfl_xor_sync(0xffffffffu, rs1, 1, 4);
        rs1 += __shfl_xor_sync(0xffffffffu, rs1, 2, 4);
        l0s = l0s * al0 + rs0;
        l1s = l1s * al1 + rs1;
#pragma unroll
        for (int nb = 0; nb < 8; ++nb) {
            oacc[nb][0] *= al0; oacc[nb][1] *= al0;
            oacc[nb][2] *= al1; oacc[nb][3] *= al1;
        }

        // O += P @ V (bf16x3)
#pragma unroll
        for (int ks = 0; ks < 4; ++ks) {
            uint32_t ph[4], pl[4];
            packhl(c[2*ks][0],   c[2*ks][1],   ph[0], pl[0]);
            packhl(c[2*ks][2],   c[2*ks][3],   ph[1], pl[1]);
            packhl(c[2*ks+1][0], c[2*ks+1][1], ph[2], pl[2]);
            packhl(c[2*ks+1][2], c[2*ks+1][3], ph[3], pl[3]);
#pragma unroll
            for (int g = 0; g < 4; ++g) {
                uint32_t vh4[4], vl4[4];
                const uint32_t vb = st + (uint32_t)(ks*16*AROWB + g*32) + v_lane;
                ldsm_x4_t(vh4, vb + SV_HI);
                ldsm_x4_t(vl4, vb + SV_LO);
                mma16816(oacc[2*g],   ph, vh4[0], vh4[1]);
                mma16816(oacc[2*g],   ph, vl4[0], vl4[1]);
                mma16816(oacc[2*g],   pl, vh4[0], vh4[1]);
                mma16816(oacc[2*g+1], ph, vh4[2], vh4[3]);
                mma16816(oacc[2*g+1], ph, vl4[2], vl4[3]);
                mma16816(oacc[2*g+1], pl, vh4[2], vh4[3]);
            }
        }

        // 2-stage ring: all warps finished reading stage (jt&1); refill it
        // with tile jt+2, then wait for tile jt+1 before the next iteration.
        __syncthreads();
        if (jt + 2 < ntiles)
            issue_kv(st, kh_g, kl_g, vh_g, vl_g, (jt + 2) * ATN, tid);
        CP_COMMIT();
        if (jt + 1 < ntiles) {
            CP_WAIT1();
            __syncthreads();
        }
    }

    // epilogue: normalize, write ao as bf16 hi/lo
    const float inv0 = 1.0f / l0s, inv1 = 1.0f / l1s;
    const int tok0 = b*SS + q0 + wid*16 + (lid >> 2);
#pragma unroll
    for (int nb = 0; nb < 8; ++nb) {
        const int col = h*DHEAD + nb*8 + 2*(lid & 3);
        uint32_t h0, lo0, h1, lo1;
        packhl(oacc[nb][0]*inv0, oacc[nb][1]*inv0, h0, lo0);
        packhl(oacc[nb][2]*inv1, oacc[nb][3]*inv1, h1, lo1);
        *(uint32_t*)(g_aohi + (size_t)tok0*DMODEL + col) = h0;
        *(uint32_t*)(g_aolo + (size_t)tok0*DMODEL + col) = lo0;
        *(uint32_t*)(g_aohi + (size_t)(tok0+8)*DMODEL + col) = h1;
        *(uint32_t*)(g_aolo + (size_t)(tok0+8)*DMODEL + col) = lo1;
    }
}

// ---------------------------------------------------------------------------
// Launch
// ---------------------------------------------------------------------------
extern "C" void kernel_launch(void* const* d_in, const int* in_sizes, int n_in,
                              void* d_out, int out_size)
{
    const float* x   = (const float*)d_in[0];
    const float* Qw  = (const float*)d_in[1];
    const float* Kw  = (const float*)d_in[2];
    const float* Vw  = (const float*)d_in[3];
    const float* Ow  = (const float*)d_in[4];
    const int*   pos = (const int*)  d_in[5];
    float*       out = (float*)d_out;

    (void)in_sizes; (void)n_in; (void)out_size;

    cudaFuncSetAttribute(qkv_gemm_kernel,
                         cudaFuncAttributeMaxDynamicSharedMemorySize, GEMM_SMEM_BYTES);
    cudaFuncSetAttribute(oproj_gemm_kernel,
                         cudaFuncAttributeMaxDynamicSharedMemorySize, GEMM_SMEM_BYTES);
    cudaFuncSetAttribute(attn_kernel,
                         cudaFuncAttributeMaxDynamicSharedMemorySize, ATTN_SMEM_B);

    rope_table_kernel<<<(SS*(DHEAD/2) + 255)/256, 256>>>(pos);

    split_x_kernel<<<(MROWS*DMODEL/4)/256, 256>>>(x);
    split_w_kernel<<<dim3((DMODEL*DMODEL/4)/256, 4), 256>>>(Qw, Kw, Vw, Ow);

    qkv_gemm_kernel<<<dim3(DMODEL/BN, MROWS/BM, 3), 256, GEMM_SMEM_BYTES>>>();

    attn_kernel<<<dim3(SS/ATM, BB*NH), 256, ATTN_SMEM_B>>>();

    oproj_gemm_kernel<<<dim3(DMODEL/BN, MROWS/BM), 256, GEMM_SMEM_BYTES>>>(out);
}

// round 16
// speedup vs baseline: 1.0252x; 1.0252x over previous
#include <cuda_runtime.h>
#include <cuda_bf16.h>
#include <math.h>
#include <cstdint>

// Problem constants
#define BB      2
#define SS      2048
#define DMODEL  1024
#define NH      16
#define DHEAD   64
#define MROWS   (BB*SS)        // 4096

// ---------------------------------------------------------------------------
// Scratch (device globals; no runtime allocation allowed)
// ---------------------------------------------------------------------------
__device__ float g_cos[SS*(DHEAD/2)];
__device__ float g_sin[SS*(DHEAD/2)];

__device__ __nv_bfloat16 g_xhi [MROWS*DMODEL];
__device__ __nv_bfloat16 g_xlo [MROWS*DMODEL];
__device__ __nv_bfloat16 g_whi[4][DMODEL*DMODEL];
__device__ __nv_bfloat16 g_wlo[4][DMODEL*DMODEL];

__device__ __nv_bfloat16 g_qhi[MROWS*DMODEL];
__device__ __nv_bfloat16 g_qlo[MROWS*DMODEL];
__device__ __nv_bfloat16 g_khi[MROWS*DMODEL];
__device__ __nv_bfloat16 g_klo[MROWS*DMODEL];
__device__ __nv_bfloat16 g_vhi[MROWS*DMODEL];
__device__ __nv_bfloat16 g_vlo[MROWS*DMODEL];
__device__ __nv_bfloat16 g_aohi[MROWS*DMODEL];
__device__ __nv_bfloat16 g_aolo[MROWS*DMODEL];

// ---------------------------------------------------------------------------
// PTX helpers (sm_80-era only; ptxas target rejects tcgen05)
// ---------------------------------------------------------------------------
__device__ __forceinline__ uint32_t smem_to_u32(const void* smem_ptr) {
    uint32_t addr;
    asm("{ .reg .u64 tmp; cvta.to.shared.u64 tmp, %1; cvt.u32.u64 %0, tmp; }"
        : "=r"(addr) : "l"(smem_ptr));
    return addr;
}

__device__ __forceinline__ void cp16(uint32_t dst, const void* src) {
    asm volatile("cp.async.cg.shared.global [%0], [%1], 16;" :: "r"(dst), "l"(src));
}
#define CP_COMMIT() asm volatile("cp.async.commit_group;" ::: "memory")
#define CP_WAIT1()  asm volatile("cp.async.wait_group 1;" ::: "memory")

__device__ __forceinline__ void ldsm_x4(uint32_t a[4], uint32_t addr) {
    asm volatile("ldmatrix.sync.aligned.m8n8.x4.shared.b16 {%0,%1,%2,%3}, [%4];"
        : "=r"(a[0]), "=r"(a[1]), "=r"(a[2]), "=r"(a[3]) : "r"(addr));
}
__device__ __forceinline__ void ldsm_x4_t(uint32_t a[4], uint32_t addr) {
    asm volatile("ldmatrix.sync.aligned.m8n8.x4.trans.shared.b16 {%0,%1,%2,%3}, [%4];"
        : "=r"(a[0]), "=r"(a[1]), "=r"(a[2]), "=r"(a[3]) : "r"(addr));
}

__device__ __forceinline__ void mma16816(float c[4], const uint32_t a[4],
                                         uint32_t b0, uint32_t b1) {
    asm volatile("mma.sync.aligned.m16n8k16.row.col.f32.bf16.bf16.f32 "
        "{%0,%1,%2,%3}, {%4,%5,%6,%7}, {%8,%9}, {%0,%1,%2,%3};"
        : "+f"(c[0]), "+f"(c[1]), "+f"(c[2]), "+f"(c[3])
        : "r"(a[0]), "r"(a[1]), "r"(a[2]), "r"(a[3]), "r"(b0), "r"(b1));
}

// split fp32 pair into bf16 hi/lo packed words
__device__ __forceinline__ void packhl(float x, float y, uint32_t& hi, uint32_t& lo) {
    __nv_bfloat16 hx = __float2bfloat16(x), hy = __float2bfloat16(y);
    __nv_bfloat16 lx = __float2bfloat16(x - __bfloat162float(hx));
    __nv_bfloat16 ly = __float2bfloat16(y - __bfloat162float(hy));
    __nv_bfloat162 H = __halves2bfloat162(hx, hy);
    __nv_bfloat162 L = __halves2bfloat162(lx, ly);
    hi = *(uint32_t*)&H; lo = *(uint32_t*)&L;
}

// ---------------------------------------------------------------------------
// RoPE table
// ---------------------------------------------------------------------------
__global__ void rope_table_kernel(const int* __restrict__ pos)
{
    int idx = blockIdx.x * 256 + threadIdx.x;
    if (idx >= SS * (DHEAD/2)) return;
    int s  = idx >> 5;
    int pr = idx & 31;
    float p   = (float)pos[s];
    float ex  = (float)(2 * pr) * (1.0f / 64.0f);
    float inv = powf(10000.0f, -ex);
    float ang = p * inv;
    float sn, cs;
    sincosf(ang, &sn, &cs);
    g_cos[idx] = cs;
    g_sin[idx] = sn;
}

// ---------------------------------------------------------------------------
// fp32 -> bf16 hi/lo split: ONE kernel for x + all 4 weights.
// z = 0 -> x (4096 blocks used); z = 1..4 -> weights (1024 blocks used).
// ---------------------------------------------------------------------------
__device__ __forceinline__ void split4(const float4 v, __nv_bfloat16* hi,
                                       __nv_bfloat16* lo, size_t i4)
{
    float f[4] = {v.x, v.y, v.z, v.w};
    __nv_bfloat16 h[4], l[4];
#pragma unroll
    for (int j = 0; j < 4; ++j) {
        h[j] = __float2bfloat16(f[j]);
        l[j] = __float2bfloat16(f[j] - __bfloat162float(h[j]));
    }
    ((__nv_bfloat162*)hi)[2*i4]   = __halves2bfloat162(h[0], h[1]);
    ((__nv_bfloat162*)hi)[2*i4+1] = __halves2bfloat162(h[2], h[3]);
    ((__nv_bfloat162*)lo)[2*i4]   = __halves2bfloat162(l[0], l[1]);
    ((__nv_bfloat162*)lo)[2*i4+1] = __halves2bfloat162(l[2], l[3]);
}

__global__ __launch_bounds__(256) void split_all_kernel(
    const float* __restrict__ x,  const float* __restrict__ Qw,
    const float* __restrict__ Kw, const float* __restrict__ Vw,
    const float* __restrict__ Ow)
{
    const int z = blockIdx.y;
    size_t i = (size_t)blockIdx.x * 256 + threadIdx.x;
    if (z == 0) {
        // x: MROWS*DMODEL/4 = 1,048,576 elems -> all 4096 blocks
        split4(((const float4*)x)[i], g_xhi, g_xlo, i);
    } else {
        // weights: DMODEL*DMODEL/4 = 262,144 elems -> first 1024 blocks
        if (blockIdx.x >= (DMODEL*DMODEL/4)/256) return;
        const float* src = (z == 1) ? Qw : (z == 2) ? Kw : (z == 3) ? Vw : Ow;
        split4(((const float4*)src)[i], g_whi[z-1], g_wlo[z-1], i);
    }
}

// ---------------------------------------------------------------------------
// HMMA bf16x3 GEMM (R7 configuration — measured best: 260.9 us qkv).
// CTA 128x256, BK=32, 3-stage cp.async pipeline, 256 threads, 8 warps of
// 64x64. One __syncthreads per K-iter. Row stride 80B.
// ---------------------------------------------------------------------------
#define BM 128
#define BN 256
#define BKG 32
#define NKIT (DMODEL/BKG)      // 32
#define ROWB 80
#define OFFA_HI 0
#define OFFA_LO (128*ROWB)             // 10240
#define OFFB_HI (2*128*ROWB)           // 20480
#define OFFB_LO (OFFB_HI + 256*ROWB)   // 40960
#define STAGEB  (OFFB_LO + 256*ROWB)   // 61440
#define NSTG 3
#define GEMM_SMEM_BYTES (NSTG*STAGEB)  // 184320

__device__ __forceinline__ void issue_stage(uint32_t sbase,
    const __nv_bfloat16* __restrict__ Ahi, const __nv_bfloat16* __restrict__ Alo,
    const __nv_bfloat16* __restrict__ Bhi, const __nv_bfloat16* __restrict__ Blo,
    int m0, int n0, int k0, int tid)
{
#pragma unroll
    for (int i2 = 0; i2 < 2; ++i2) {
        const int i = tid + i2 * 256;
        const int r = i >> 2, c = i & 3;
        const uint32_t so = (uint32_t)(r * ROWB + c * 16);
        const size_t go = (size_t)(m0 + r) * DMODEL + k0 + c * 8;
        cp16(sbase + OFFA_HI + so, Ahi + go);
        cp16(sbase + OFFA_LO + so, Alo + go);
    }
#pragma unroll
    for (int i2 = 0; i2 < 4; ++i2) {
        const int i = tid + i2 * 256;
        const int r = i >> 2, c = i & 3;
        const uint32_t so = (uint32_t)(r * ROWB + c * 16);
        const size_t go = (size_t)(n0 + r) * DMODEL + k0 + c * 8;
        cp16(sbase + OFFB_HI + so, Bhi + go);
        cp16(sbase + OFFB_LO + so, Blo + go);
    }
}

__device__ __forceinline__ void tc_gemm(
    const __nv_bfloat16* __restrict__ Ahi, const __nv_bfloat16* __restrict__ Alo,
    const __nv_bfloat16* __restrict__ Bhi, const __nv_bfloat16* __restrict__ Blo,
    float* __restrict__ Cf, __nv_bfloat16* __restrict__ Chi,
    __nv_bfloat16* __restrict__ Clo, const bool do_rope)
{
    extern __shared__ char gsm[];
    const uint32_t sb = smem_to_u32(gsm);

    const int tid = threadIdx.x;
    const int wid = tid >> 5;
    const int lid = tid & 31;
    const int wm  = wid & 1;      // 2 row-bands of 64
    const int wn  = wid >> 1;     // 4 col-bands of 64
    const int m0  = blockIdx.y * BM;
    const int n0  = blockIdx.x * BN;

    float acc[4][8][4];
#pragma unroll
    for (int mt = 0; mt < 4; ++mt)
#pragma unroll
        for (int nb = 0; nb < 8; ++nb)
#pragma unroll
            for (int j = 0; j < 4; ++j) acc[mt][nb][j] = 0.0f;

    const uint32_t a_lane = (uint32_t)((lid & 15) * ROWB + (lid >> 4) * 16);
    const uint32_t b_lane = (uint32_t)(((lid & 7) + ((lid >> 4) << 3)) * ROWB
                                       + ((lid >> 3) & 1) * 16);

    issue_stage(sb,          Ahi, Alo, Bhi, Blo, m0, n0, 0,   tid); CP_COMMIT();
    issue_stage(sb + STAGEB, Ahi, Alo, Bhi, Blo, m0, n0, BKG, tid); CP_COMMIT();

    int stg = 0;
#pragma unroll 1
    for (int it = 0; it < NKIT; ++it) {
        CP_WAIT1();
        __syncthreads();

        const uint32_t st = sb + (uint32_t)stg * STAGEB;
#pragma unroll
        for (int ks = 0; ks < 2; ++ks) {
            const uint32_t kso = (uint32_t)(ks * 32);   // 16 bf16 = 32 B
            uint32_t ah[4][4], al[4][4], bh[4][4], bl[4][4];
#pragma unroll
            for (int mt = 0; mt < 4; ++mt) {
                const uint32_t abase = st + (uint32_t)((wm*64 + mt*16) * ROWB) + kso + a_lane;
                ldsm_x4(ah[mt], abase + OFFA_HI);
                ldsm_x4(al[mt], abase + OFFA_LO);
            }
#pragma unroll
            for (int p = 0; p < 4; ++p) {
                const uint32_t bbase = st + (uint32_t)((wn*64 + p*16) * ROWB) + kso + b_lane;
                ldsm_x4(bh[p], bbase + OFFB_HI);
                ldsm_x4(bl[p], bbase + OFFB_LO);
            }
#pragma unroll
            for (int mt = 0; mt < 4; ++mt)
#pragma unroll
                for (int nb = 0; nb < 8; ++nb) {
                    const int p = nb >> 1, o = (nb & 1) * 2;
                    mma16816(acc[mt][nb], ah[mt], bh[p][o], bh[p][o+1]);
                    mma16816(acc[mt][nb], ah[mt], bl[p][o], bl[p][o+1]);
                    mma16816(acc[mt][nb], al[mt], bh[p][o], bh[p][o+1]);
                }
        }

        // Refill stage (stg+2)%3 == (stg-1)%3: readers finished before this
        // iteration's top barrier, so one barrier per iter suffices.
        if (it + 2 < NKIT) {
            int rstg = stg + 2; if (rstg >= NSTG) rstg -= NSTG;
            issue_stage(sb + (uint32_t)rstg * STAGEB,
                        Ahi, Alo, Bhi, Blo, m0, n0, (it + 2) * BKG, tid);
        }
        CP_COMMIT();
        if (++stg == NSTG) stg = 0;
    }

#pragma unroll
    for (int mt = 0; mt < 4; ++mt) {
        const int row0 = m0 + wm*64 + mt*16 + (lid >> 2);
#pragma unroll
        for (int nb = 0; nb < 8; ++nb) {
            const int col = n0 + wn*64 + nb*8 + 2*(lid & 3);
            float v0 = acc[mt][nb][0], v1 = acc[mt][nb][1];
            float v2 = acc[mt][nb][2], v3 = acc[mt][nb][3];
            if (do_rope) {
                const int pr = (col & 63) >> 1;
                {
                    const int s = row0 & (SS - 1);
                    const float cs = g_cos[s*32 + pr], sn = g_sin[s*32 + pr];
                    const float x0 = v0, x1 = v1;
                    v0 = x0*cs - x1*sn;  v1 = x0*sn + x1*cs;
                }
                {
                    const int s = (row0 + 8) & (SS - 1);
                    const float cs = g_cos[s*32 + pr], sn = g_sin[s*32 + pr];
                    const float x0 = v2, x1 = v3;
                    v2 = x0*cs - x1*sn;  v3 = x0*sn + x1*cs;
                }
            }
            if (Cf) {
                *(float2*)(Cf + (size_t)row0       * DMODEL + col) = make_float2(v0, v1);
                *(float2*)(Cf + (size_t)(row0 + 8) * DMODEL + col) = make_float2(v2, v3);
            } else {
                uint32_t h0, l0, h1, l1;
                packhl(v0, v1, h0, l0);
                packhl(v2, v3, h1, l1);
                *(uint32_t*)(Chi + (size_t)row0       * DMODEL + col) = h0;
                *(uint32_t*)(Clo + (size_t)row0       * DMODEL + col) = l0;
                *(uint32_t*)(Chi + (size_t)(row0 + 8) * DMODEL + col) = h1;
                *(uint32_t*)(Clo + (size_t)(row0 + 8) * DMODEL + col) = l1;
            }
        }
    }
}

__global__ __launch_bounds__(256)
void qkv_gemm_kernel()
{
    const int z = blockIdx.z;
    __nv_bfloat16* Chi = (z == 0) ? g_qhi : (z == 1) ? g_khi : g_vhi;
    __nv_bfloat16* Clo = (z == 0) ? g_qlo : (z == 1) ? g_klo : g_vlo;
    tc_gemm(g_xhi, g_xlo, g_whi[z], g_wlo[z], nullptr, Chi, Clo, z < 2);
}

__global__ __launch_bounds__(256)
void oproj_gemm_kernel(float* __restrict__ out)
{
    tc_gemm(g_aohi, g_aolo, g_whi[3], g_wlo[3], out, nullptr, nullptr, false);
}

// ---------------------------------------------------------------------------
// Flash attention with HMMA bf16x3 (causal, online softmax) — R7 verbatim:
// CTA 128 q-rows (8 warps x 16), key tiles of 64, 3-stage cp.async KV ring,
// ONE __syncthreads per key tile, Q fragments held in registers.
// ---------------------------------------------------------------------------
#define ATM 128
#define ATN 64
#define AROWB 144
#define AQHI_OFF 0
#define AQLO_OFF (128*AROWB)            // 18432
#define ASTG_OFF (2*128*AROWB)          // 36864
#define SK_HI 0
#define SK_LO (64*AROWB)                // 9216
#define SV_HI (2*64*AROWB)
#define SV_LO (3*64*AROWB)
#define ASTGB (4*64*AROWB)              // 36864
#define ANSTG 3
#define ATTN_SMEM_B (ASTG_OFF + ANSTG*ASTGB)  // 147456

__device__ __forceinline__ void issue_kv(uint32_t st,
    const __nv_bfloat16* __restrict__ kh, const __nv_bfloat16* __restrict__ kl,
    const __nv_bfloat16* __restrict__ vh, const __nv_bfloat16* __restrict__ vl,
    int n0, int tid)
{
#pragma unroll
    for (int i2 = 0; i2 < 2; ++i2) {
        const int i = tid + i2 * 256;
        const int r = i >> 3, c = i & 7;
        const size_t go = (size_t)(n0 + r) * DMODEL + c * 8;
        const uint32_t so = (uint32_t)(r * AROWB + c * 16);
        cp16(st + SK_HI + so, kh + go);
        cp16(st + SK_LO + so, kl + go);
        cp16(st + SV_HI + so, vh + go);
        cp16(st + SV_LO + so, vl + go);
    }
}

__global__ __launch_bounds__(256)
void attn_kernel()
{
    extern __shared__ char smb[];
    const uint32_t sb = smem_to_u32(smb);
    const int tid = threadIdx.x;
    const int wid = tid >> 5;
    const int lid = tid & 31;
    const int bh  = blockIdx.y;
    const int b   = bh >> 4, h = bh & 15;
    const int bx  = (int)gridDim.x - 1 - (int)blockIdx.x;   // long blocks first
    const int q0  = bx * ATM;

    const size_t hb = (size_t)(b*SS)*DMODEL + h*DHEAD;
    const __nv_bfloat16* qh_g = g_qhi + hb + (size_t)q0*DMODEL;
    const __nv_bfloat16* ql_g = g_qlo + hb + (size_t)q0*DMODEL;
    const __nv_bfloat16* kh_g = g_khi + hb;
    const __nv_bfloat16* kl_g = g_klo + hb;
    const __nv_bfloat16* vh_g = g_vhi + hb;
    const __nv_bfloat16* vl_g = g_vlo + hb;

    // Q loads (hi+lo) in group 0 along with KV stage 0
#pragma unroll
    for (int i2 = 0; i2 < 4; ++i2) {
        const int i = tid + i2 * 256;
        const int r = i >> 3, c = i & 7;
        const size_t go = (size_t)r * DMODEL + c * 8;
        const uint32_t so = (uint32_t)(r * AROWB + c * 16);
        cp16(sb + AQHI_OFF + so, qh_g + go);
        cp16(sb + AQLO_OFF + so, ql_g + go);
    }
    issue_kv(sb + ASTG_OFF, kh_g, kl_g, vh_g, vl_g, 0, tid);
    CP_COMMIT();

    const int ntiles = 2*bx + 2;
    issue_kv(sb + ASTG_OFF + ASTGB, kh_g, kl_g, vh_g, vl_g, ATN, tid);
    CP_COMMIT();

    CP_WAIT1();
    __syncthreads();

    // Q fragments (held in registers for the whole kernel)
    uint32_t qfh[4][4], qfl[4][4];
    const uint32_t a_lane = (uint32_t)((lid & 15)*AROWB + (lid >> 4)*16);
#pragma unroll
    for (int ks = 0; ks < 4; ++ks) {
        const uint32_t ab = sb + (uint32_t)(wid*16*AROWB + ks*32) + a_lane;
        ldsm_x4(qfh[ks], ab + AQHI_OFF);
        ldsm_x4(qfl[ks], ab + AQLO_OFF);
    }

    const uint32_t b_lane = (uint32_t)(((lid & 7) + ((lid >> 4) << 3))*AROWB + ((lid >> 3) & 1)*16);
    const uint32_t v_lane = (uint32_t)(((lid & 7) + (((lid >> 3) & 1) << 3))*AROWB + (lid >> 4)*16);
    const int rowq = q0 + wid*16 + (lid >> 2);

    float m0v = -1e30f, m1v = -1e30f, l0s = 0.0f, l1s = 0.0f;
    float oacc[8][4];
#pragma unroll
    for (int nb = 0; nb < 8; ++nb)
#pragma unroll
        for (int j = 0; j < 4; ++j) oacc[nb][j] = 0.0f;

    int stg = 0;   // ring position of current tile

#pragma unroll 1
    for (int jt = 0; jt < ntiles; ++jt) {
        if (jt > 0) { CP_WAIT1(); __syncthreads(); }
        const uint32_t st = sb + ASTG_OFF + (uint32_t)stg * ASTGB;

        // S = Q @ K^T (bf16x3)
        float c[8][4];
#pragma unroll
        for (int nb = 0; nb < 8; ++nb)
#pragma unroll
            for (int j = 0; j < 4; ++j) c[nb][j] = 0.0f;

#pragma unroll
        for (int ks = 0; ks < 4; ++ks) {
#pragma unroll
            for (int g = 0; g < 4; ++g) {
                uint32_t kh4[4], kl4[4];
                const uint32_t kb = st + (uint32_t)(g*16*AROWB + ks*32) + b_lane;
                ldsm_x4(kh4, kb + SK_HI);
                ldsm_x4(kl4, kb + SK_LO);
#pragma unroll
                for (int hf = 0; hf < 2; ++hf) {
                    const int nb = g*2 + hf;
                    mma16816(c[nb], qfh[ks], kh4[hf*2], kh4[hf*2+1]);
                    mma16816(c[nb], qfh[ks], kl4[hf*2], kl4[hf*2+1]);
                    mma16816(c[nb], qfl[ks], kh4[hf*2], kh4[hf*2+1]);
                }
            }
        }

        // online softmax (rows rowq, rowq+8)
        const int n0 = jt * ATN;
        const bool nm = (n0 + ATN > q0 + wid*16);
        float rm0 = -1e30f, rm1 = -1e30f;
#pragma unroll
        for (int nb = 0; nb < 8; ++nb)
#pragma unroll
            for (int j = 0; j < 4; ++j) {
                float sv = c[nb][j] * 0.125f;
                if (nm) {
                    const int col = n0 + nb*8 + 2*(lid & 3) + (j & 1);
                    const int row = rowq + (j >> 1) * 8;
                    if (col > row) sv = -1e30f;
                }
                c[nb][j] = sv;
                if (j < 2) rm0 = fmaxf(rm0, sv); else rm1 = fmaxf(rm1, sv);
            }
        rm0 = fmaxf(rm0, __shfl_xor_sync(0xffffffffu, rm0, 1, 4));
        rm0 = fmaxf(rm0, __shfl_xor_sync(0xffffffffu, rm0, 2, 4));
        rm1 = fmaxf(rm1, __shfl_xor_sync(0xffffffffu, rm1, 1, 4));
        rm1 = fmaxf(rm1, __shfl_xor_sync(0xffffffffu, rm1, 2, 4));
        const float mn0 = fmaxf(m0v, rm0), mn1 = fmaxf(m1v, rm1);
        const float al0 = __expf(m0v - mn0), al1 = __expf(m1v - mn1);
        m0v = mn0; m1v = mn1;
        float rs0 = 0.0f, rs1 = 0.0f;
#pragma unroll
        for (int nb = 0; nb < 8; ++nb) {
            float p0 = __expf(c[nb][0] - mn0);
            float p1 = __expf(c[nb][1] - mn0);
            float p2 = __expf(c[nb][2] - mn1);
            float p3 = __expf(c[nb][3] - mn1);
            c[nb][0] = p0; c[nb][1] = p1; c[nb][2] = p2; c[nb][3] = p3;
            rs0 += p0 + p1; rs1 += p2 + p3;
        }
        rs0 += __shfl_xor_sync(0xffffffffu, rs0, 1, 4);
        rs0 += __shfl_xor_sync(0xffffffffu, rs0, 2, 4);
        rs1 += __shfl_xor_sync(0xffffffffu, rs1, 1, 4);
        rs1 += __shfl_xor_sync(0xffffffffu, rs1, 2, 4);
        l0s = l0s * al0 + rs0;
        l1s = l1s * al1 + rs1;
#pragma unroll
        for (int nb = 0; nb < 8; ++nb) {
            oacc[nb][0] *= al0; oacc[nb][1] *= al0;
            oacc[nb][2] *= al1; oacc[nb][3] *= al1;
        }

        // O += P @ V (bf16x3, P fragments built in-register)
#pragma unroll
        for (int ks = 0; ks < 4; ++ks) {
            uint32_t ph[4], pl[4];
            packhl(c[2*ks][0],   c[2*ks][1],   ph[0], pl[0]);
            packhl(c[2*ks][2],   c[2*ks][3],   ph[1], pl[1]);
            packhl(c[2*ks+1][0], c[2*ks+1][1], ph[2], pl[2]);
            packhl(c[2*ks+1][2], c[2*ks+1][3], ph[3], pl[3]);
#pragma unroll
            for (int g = 0; g < 4; ++g) {
                uint32_t vh4[4], vl4[4];
                const uint32_t vb = st + (uint32_t)(ks*16*AROWB + g*32) + v_lane;
                ldsm_x4_t(vh4, vb + SV_HI);
                ldsm_x4_t(vl4, vb + SV_LO);
                mma16816(oacc[2*g],   ph, vh4[0], vh4[1]);
                mma16816(oacc[2*g],   ph, vl4[0], vl4[1]);
                mma16816(oacc[2*g],   pl, vh4[0], vh4[1]);
                mma16816(oacc[2*g+1], ph, vh4[2], vh4[3]);
                mma16816(oacc[2*g+1], ph, vl4[2], vl4[3]);
                mma16816(oacc[2*g+1], pl, vh4[2], vh4[3]);
            }
        }

        // Refill stage (stg+2)%3 == (stg-1)%3: readers finished before this
        // iteration's top barrier. No second barrier needed.
        if (jt + 2 < ntiles) {
            int rstg = stg + 2; if (rstg >= ANSTG) rstg -= ANSTG;
            issue_kv(sb + ASTG_OFF + (uint32_t)rstg * ASTGB,
                     kh_g, kl_g, vh_g, vl_g, (jt + 2) * ATN, tid);
        }
        CP_COMMIT();
        if (++stg == ANSTG) stg = 0;
    }

    // epilogue: normalize, write ao as bf16 hi/lo
    const float inv0 = 1.0f / l0s, inv1 = 1.0f / l1s;
    const int tok0 = b*SS + q0 + wid*16 + (lid >> 2);
#pragma unroll
    for (int nb = 0; nb < 8; ++nb) {
        const int col = h*DHEAD + nb*8 + 2*(lid & 3);
        uint32_t h0, lo0, h1, lo1;
        packhl(oacc[nb][0]*inv0, oacc[nb][1]*inv0, h0, lo0);
        packhl(oacc[nb][2]*inv1, oacc[nb][3]*inv1, h1, lo1);
        *(uint32_t*)(g_aohi + (size_t)tok0*DMODEL + col) = h0;
        *(uint32_t*)(g_aolo + (size_t)tok0*DMODEL + col) = lo0;
        *(uint32_t*)(g_aohi + (size_t)(tok0+8)*DMODEL + col) = h1;
        *(uint32_t*)(g_aolo + (size_t)(tok0+8)*DMODEL + col) = lo1;
    }
}

// ---------------------------------------------------------------------------
// Launch
// ---------------------------------------------------------------------------
extern "C" void kernel_launch(void* const* d_in, const int* in_sizes, int n_in,
                              void* d_out, int out_size)
{
    const float* x   = (const float*)d_in[0];
    const float* Qw  = (const float*)d_in[1];
    const float* Kw  = (const float*)d_in[2];
    const float* Vw  = (const float*)d_in[3];
    const float* Ow  = (const float*)d_in[4];
    const int*   pos = (const int*)  d_in[5];
    float*       out = (float*)d_out;

    (void)in_sizes; (void)n_in; (void)out_size;

    cudaFuncSetAttribute(qkv_gemm_kernel,
                         cudaFuncAttributeMaxDynamicSharedMemorySize, GEMM_SMEM_BYTES);
    cudaFuncSetAttribute(oproj_gemm_kernel,
                         cudaFuncAttributeMaxDynamicSharedMemorySize, GEMM_SMEM_BYTES);
    cudaFuncSetAttribute(attn_kernel,
                         cudaFuncAttributeMaxDynamicSharedMemorySize, ATTN_SMEM_B);

    rope_table_kernel<<<(SS*(DHEAD/2) + 255)/256, 256>>>(pos);

    split_all_kernel<<<dim3((MROWS*DMODEL/4)/256, 5), 256>>>(x, Qw, Kw, Vw, Ow);

    qkv_gemm_kernel<<<dim3(DMODEL/BN, MROWS/BM, 3), 256, GEMM_SMEM_BYTES>>>();

    attn_kernel<<<dim3(SS/ATM, BB*NH), 256, ATTN_SMEM_B>>>();

    oproj_gemm_kernel<<<dim3(DMODEL/BN, MROWS/BM), 256, GEMM_SMEM_BYTES>>>(out);
}